// round 6
// baseline (speedup 1.0000x reference)
#include <cuda_runtime.h>
#include <cuda_fp16.h>
#include <cstdint>

#define NN 50000
#define NE 200000
#define DD 128
#define RR 4
#define HH 64
#define TE 64            // rows (edges/nodes) per tile (M)
#define XSH 136          // stride (halves) for 128-wide buffers; /2 = 68 ≡ 4 mod 32
#define HSH 72           // stride (halves) for 64-wide buffers;   /2 = 36 ≡ 4 mod 32
#define NTHREADS 256
#define NSM 152

__device__ float g_acc[NN * HH];
__device__ int   g_bucket[RR * NE];
__device__ int   g_cnt[RR];

__global__ void bin_kernel(const int* __restrict__ etype) {
    __shared__ int s_cnt[RR];
    __shared__ int s_base[RR];
    int t = threadIdx.x;
    if (t < RR) s_cnt[t] = 0;
    __syncthreads();
    int e = blockIdx.x * blockDim.x + t;
    int r = -1, pos = 0;
    if (e < NE) { r = etype[e]; pos = atomicAdd(&s_cnt[r], 1); }
    __syncthreads();
    if (t < RR) s_base[t] = atomicAdd(&g_cnt[t], s_cnt[t]);
    __syncthreads();
    if (r >= 0) g_bucket[r * NE + s_base[r] + pos] = e;
}

// ---- helpers ----------------------------------------------------------------
__device__ __forceinline__ void mma_f16(float c[4], uint32_t a0, uint32_t a1,
                                        uint32_t a2, uint32_t a3,
                                        uint32_t b0, uint32_t b1) {
    asm volatile(
        "mma.sync.aligned.m16n8k16.row.col.f32.f16.f16.f32 "
        "{%0,%1,%2,%3}, {%4,%5,%6,%7}, {%8,%9}, {%0,%1,%2,%3};"
        : "+f"(c[0]), "+f"(c[1]), "+f"(c[2]), "+f"(c[3])
        : "r"(a0), "r"(a1), "r"(a2), "r"(a3), "r"(b0), "r"(b1));
}
__device__ __forceinline__ void red2(float* p, float x, float y) {
    asm volatile("red.global.add.v2.f32 [%0], {%1, %2};"
                 :: "l"(p), "f"(x), "f"(y) : "memory");
}
// Pair barrier: 2 warps (64 threads) sharing one 16-row block. ids 1..4.
__device__ __forceinline__ void pbar(int p) {
    asm volatile("bar.sync %0, 64;" :: "r"(p + 1) : "memory");
}

// Warp GEMM over K (fp16 in, fp32 acc). act: [M][AST] halves, wT: [N][KS] halves.
template<int K, int AST, int KS, int NCH>
__device__ __forceinline__ void wgemm(const __half* __restrict__ act,
                                      const __half* __restrict__ wT,
                                      int mrow0, int ncol0, int g, int tig,
                                      float c[NCH][4]) {
    const __half* ar0 = act + (mrow0 + g) * AST + 2 * tig;
    const __half* ar1 = ar0 + 8 * AST;
    #pragma unroll
    for (int k0 = 0; k0 < K; k0 += 16) {
        uint32_t a0 = *(const uint32_t*)(ar0 + k0);
        uint32_t a1 = *(const uint32_t*)(ar1 + k0);
        uint32_t a2 = *(const uint32_t*)(ar0 + k0 + 8);
        uint32_t a3 = *(const uint32_t*)(ar1 + k0 + 8);
        #pragma unroll
        for (int j = 0; j < NCH; j++) {
            const __half* wn = wT + (ncol0 + j * 8 + g) * KS + k0 + 2 * tig;
            uint32_t b0 = *(const uint32_t*)(wn);
            uint32_t b1 = *(const uint32_t*)(wn + 8);
            mma_f16(c[j], a0, a1, a2, a3, b0, b1);
        }
    }
}

template<int NCH>
__device__ __forceinline__ void epi_store(float c[NCH][4], __half* outb, int OST,
                                          const float* bias, int mrow0, int ncol0,
                                          int g, int tig) {
    #pragma unroll
    for (int j = 0; j < NCH; j++) {
        int col = ncol0 + j * 8 + 2 * tig;
        float b0 = bias[col], b1 = bias[col + 1];
        *(half2*)(outb + (mrow0 + g) * OST + col) =
            __floats2half2_rn(fmaxf(c[j][0] + b0, 0.f), fmaxf(c[j][1] + b1, 0.f));
        *(half2*)(outb + (mrow0 + g + 8) * OST + col) =
            __floats2half2_rn(fmaxf(c[j][2] + b0, 0.f), fmaxf(c[j][3] + b1, 0.f));
    }
}

// SMEM layouts (byte offsets)
#define E_W1T 0
#define E_W2T (E_W1T + HH * XSH * 2)
#define E_W3T (E_W2T + HH * HSH * 2)
#define E_WNT (E_W3T + DD * HSH * 2)
#define E_SX  (E_WNT + HH * XSH * 2)
#define E_SH1 (E_SX + TE * XSH * 2)
#define E_SH2 (E_SH1 + TE * HSH * 2)
#define E_SB1 (E_SH2 + TE * HSH * 2)
#define E_SB2 (E_SB1 + HH * 4)
#define E_SB3 (E_SB2 + HH * 4)
#define E_SRC (E_SB3 + DD * 4)
#define E_DST (E_SRC + TE * 4)
#define E_TOTAL (E_DST + TE * 4)          // 99840 B -> occ 2

#define N_W1T 0
#define N_W2T (N_W1T + HH * XSH * 2)
#define N_W3T (N_W2T + HH * HSH * 2)
#define N_SX  (N_W3T + DD * HSH * 2)
#define N_SH1 (N_SX + TE * XSH * 2)
#define N_SH2 (N_SH1 + TE * HSH * 2)
#define N_SB1 (N_SH2 + TE * HSH * 2)
#define N_SB2 (N_SB1 + HH * 4)
#define N_SB3 (N_SB2 + HH * 4)
#define N_TOTAL (N_SB3 + DD * 4)          // 81920 B -> occ 2

// ---------------------------------------------------------------------------
// Edge kernel. Warp-pair pipelines: pair p owns rows [16p,16p+16); the two
// warps in a pair split the N dimension. Only pair barriers between stages.
// ---------------------------------------------------------------------------
__global__ __launch_bounds__(NTHREADS, 2)
void edge_kernel(const float* __restrict__ nf,
                 const int* __restrict__ esrc, const int* __restrict__ edst,
                 const float* __restrict__ Wr1, const float* __restrict__ br1,
                 const float* __restrict__ Wr2, const float* __restrict__ br2,
                 const float* __restrict__ Wr3, const float* __restrict__ br3,
                 const float* __restrict__ Wn1) {
    extern __shared__ __align__(16) char smraw[];
    __half* sW1T = (__half*)(smraw + E_W1T);
    __half* sW2T = (__half*)(smraw + E_W2T);
    __half* sW3T = (__half*)(smraw + E_W3T);
    __half* sWnT = (__half*)(smraw + E_WNT);
    __half* sX   = (__half*)(smraw + E_SX);
    __half* sH1  = (__half*)(smraw + E_SH1);
    __half* sH2  = (__half*)(smraw + E_SH2);
    float*  sb1  = (float*)(smraw + E_SB1);
    float*  sb2  = (float*)(smraw + E_SB2);
    float*  sb3  = (float*)(smraw + E_SB3);
    int*    sSrc = (int*)(smraw + E_SRC);
    int*    sDst = (int*)(smraw + E_DST);

    const int t     = threadIdx.x;
    const int rel   = blockIdx.x & (RR - 1);
    const int bslot = blockIdx.x >> 2;
    const int nb    = gridDim.x >> 2;

    const float* gW1 = Wr1 + rel * DD * HH;
    const float* gW2 = Wr2 + rel * HH * HH;
    const float* gW3 = Wr3 + rel * HH * DD;
    const float* gWn = Wn1 + (1 + rel) * DD * HH;
    for (int i = t; i < DD * HH; i += NTHREADS) {
        int d = i >> 6, h = i & 63;
        sW1T[h * XSH + d] = __float2half(gW1[i]);
        sWnT[h * XSH + d] = __float2half(gWn[i]);
    }
    for (int i = t; i < HH * HH; i += NTHREADS) {
        int k = i >> 6, h = i & 63;
        sW2T[h * HSH + k] = __float2half(gW2[i]);
    }
    for (int i = t; i < HH * DD; i += NTHREADS) {
        int k = i >> 7, d = i & 127;
        sW3T[d * HSH + k] = __float2half(gW3[i]);
    }
    if (t < HH) { sb1[t] = br1[rel * HH + t]; sb2[t] = br2[rel * HH + t]; }
    if (t < DD) { sb3[t] = br3[rel * DD + t]; }
    __syncthreads();    // weights/biases visible to all pairs; only barrier 0 use

    const int cnt    = g_cnt[rel];
    const int ntiles = (cnt + TE - 1) / TE;

    const int lane = t & 31, w = t >> 5;
    const int g = lane >> 2, tig = lane & 3;
    const int p    = w >> 1;            // pair id 0..3
    const int half = w & 1;             // n-half within pair
    const int mrow = p * 16;
    const int nc4  = half * 32;
    const int nc8  = half * 64;
    const int tp   = t & 63;            // thread-in-pair
    const int grow = mrow + (tp >> 2), gj = tp & 3;

    for (int tile = bslot; tile < ntiles; tile += nb) {
        // pair-local: previous iteration's L4 finished reading sX rows of p
        if (tp < 16) {
            int idx = tile * TE + mrow + tp;
            if (idx < cnt) {
                int e = g_bucket[rel * NE + idx];
                sSrc[mrow + tp] = esrc[e];
                sDst[mrow + tp] = edst[e];
            } else { sSrc[mrow + tp] = 0; sDst[mrow + tp] = -1; }
        }
        pbar(p);

        // Gather pair's 16 rows of x_src -> fp16
        {
            const float* xr = nf + (long)sSrc[grow] * DD;
            __half* dr = sX + grow * XSH;
            #pragma unroll
            for (int i = 0; i < 8; i++) {
                int d0 = gj * 4 + i * 16;
                float4 v = *(const float4*)(xr + d0);
                *(half2*)(dr + d0)     = __floats2half2_rn(v.x, v.y);
                *(half2*)(dr + d0 + 2) = __floats2half2_rn(v.z, v.w);
            }
        }
        pbar(p);

        { // L1: [16,128]@[128,64] per pair
            float c[4][4] = {};
            wgemm<DD, XSH, XSH, 4>(sX, sW1T, mrow, nc4, g, tig, c);
            epi_store<4>(c, sH1, HSH, sb1, mrow, nc4, g, tig);
        }
        pbar(p);

        { // L2: [16,64]@[64,64]
            float c[4][4] = {};
            wgemm<HH, HSH, HSH, 4>(sH1, sW2T, mrow, nc4, g, tig, c);
            epi_store<4>(c, sH2, HSH, sb2, mrow, nc4, g, tig);
        }
        pbar(p);

        { // L3: [16,64]@[64,128] -> msg into sX
            float c[8][4] = {};
            wgemm<HH, HSH, HSH, 8>(sH2, sW3T, mrow, nc8, g, tig, c);
            epi_store<8>(c, sX, XSH, sb3, mrow, nc8, g, tig);
        }
        pbar(p);

        { // L4: [16,128]@[128,64] -> reductions into g_acc
            float c[4][4] = {};
            wgemm<DD, XSH, XSH, 4>(sX, sWnT, mrow, nc4, g, tig, c);
            int d0 = sDst[mrow + g];
            int d1 = sDst[mrow + g + 8];
            #pragma unroll
            for (int j = 0; j < 4; j++) {
                int col = nc4 + j * 8 + 2 * tig;
                if (d0 >= 0) red2(g_acc + (long)d0 * HH + col, c[j][0], c[j][1]);
                if (d1 >= 0) red2(g_acc + (long)d1 * HH + col, c[j][2], c[j][3]);
            }
        }
        pbar(p);    // protect sX/sSrc before next iteration overwrites
    }
}

// ---------------------------------------------------------------------------
// Node kernel, same pair-pipeline structure.
// ---------------------------------------------------------------------------
__global__ __launch_bounds__(NTHREADS, 2)
void node_kernel(const float* __restrict__ nf,
                 const float* __restrict__ Wn1, const float* __restrict__ bn1,
                 const float* __restrict__ Wn2, const float* __restrict__ bn2,
                 const float* __restrict__ Wn3, const float* __restrict__ bn3,
                 float* __restrict__ out) {
    extern __shared__ __align__(16) char smraw[];
    __half* sW1T = (__half*)(smraw + N_W1T);
    __half* sW2T = (__half*)(smraw + N_W2T);
    __half* sW3T = (__half*)(smraw + N_W3T);
    __half* sX   = (__half*)(smraw + N_SX);
    __half* sH1  = (__half*)(smraw + N_SH1);
    __half* sH2  = (__half*)(smraw + N_SH2);
    float*  sb1  = (float*)(smraw + N_SB1);
    float*  sb2  = (float*)(smraw + N_SB2);
    float*  sb3  = (float*)(smraw + N_SB3);

    const int t = threadIdx.x;
    for (int i = t; i < DD * HH; i += NTHREADS) {
        int d = i >> 6, h = i & 63;
        sW1T[h * XSH + d] = __float2half(Wn1[i]);
    }
    for (int i = t; i < HH * HH; i += NTHREADS) {
        int k = i >> 6, h = i & 63;
        sW2T[h * HSH + k] = __float2half(Wn2[i]);
    }
    for (int i = t; i < HH * DD; i += NTHREADS) {
        int k = i >> 7, d = i & 127;
        sW3T[d * HSH + k] = __float2half(Wn3[i]);
    }
    if (t < HH) { sb1[t] = bn1[t]; sb2[t] = bn2[t]; }
    if (t < DD) sb3[t] = bn3[t];
    __syncthreads();

    const int ntiles = (NN + TE - 1) / TE;
    const int lane = t & 31, w = t >> 5;
    const int g = lane >> 2, tig = lane & 3;
    const int p    = w >> 1;
    const int half = w & 1;
    const int mrow = p * 16;
    const int nc4  = half * 32;
    const int nc8  = half * 64;
    const int tp   = t & 63;
    const int grow = mrow + (tp >> 2), gj = tp & 3;

    for (int tile = blockIdx.x; tile < ntiles; tile += gridDim.x) {
        const int base = tile * TE;
        {
            const int n = base + grow;
            __half* dr = sX + grow * XSH;
            if (n < NN) {
                const float* xr = nf + (long)n * DD;
                #pragma unroll
                for (int i = 0; i < 8; i++) {
                    int d0 = gj * 4 + i * 16;
                    float4 v = *(const float4*)(xr + d0);
                    *(half2*)(dr + d0) =
                        __floats2half2_rn(fmaxf(v.x, 0.f), fmaxf(v.y, 0.f));
                    *(half2*)(dr + d0 + 2) =
                        __floats2half2_rn(fmaxf(v.z, 0.f), fmaxf(v.w, 0.f));
                }
            } else {
                #pragma unroll
                for (int i = 0; i < 8; i++) {
                    int d0 = gj * 4 + i * 16;
                    *(half2*)(dr + d0)     = __floats2half2_rn(0.f, 0.f);
                    *(half2*)(dr + d0 + 2) = __floats2half2_rn(0.f, 0.f);
                }
            }
        }
        pbar(p);

        { // L1 + g_acc + bias
            float c[4][4] = {};
            wgemm<DD, XSH, XSH, 4>(sX, sW1T, mrow, nc4, g, tig, c);
            int n0 = base + mrow + g;
            int n1 = n0 + 8;
            #pragma unroll
            for (int j = 0; j < 4; j++) {
                int col = nc4 + j * 8 + 2 * tig;
                float b0 = sb1[col], b1 = sb1[col + 1];
                __half* o0 = sH1 + (mrow + g) * HSH + col;
                __half* o1 = sH1 + (mrow + g + 8) * HSH + col;
                if (n0 < NN) {
                    float2 ga = *(const float2*)(g_acc + (long)n0 * HH + col);
                    *(half2*)o0 = __floats2half2_rn(
                        fmaxf(c[j][0] + ga.x + b0, 0.f),
                        fmaxf(c[j][1] + ga.y + b1, 0.f));
                } else *(half2*)o0 = __floats2half2_rn(0.f, 0.f);
                if (n1 < NN) {
                    float2 ga = *(const float2*)(g_acc + (long)n1 * HH + col);
                    *(half2*)o1 = __floats2half2_rn(
                        fmaxf(c[j][2] + ga.x + b0, 0.f),
                        fmaxf(c[j][3] + ga.y + b1, 0.f));
                } else *(half2*)o1 = __floats2half2_rn(0.f, 0.f);
            }
        }
        pbar(p);

        { // L2
            float c[4][4] = {};
            wgemm<HH, HSH, HSH, 4>(sH1, sW2T, mrow, nc4, g, tig, c);
            epi_store<4>(c, sH2, HSH, sb2, mrow, nc4, g, tig);
        }
        pbar(p);

        { // L3 -> out (fp32)
            float c[8][4] = {};
            wgemm<HH, HSH, HSH, 8>(sH2, sW3T, mrow, nc8, g, tig, c);
            int n0 = base + mrow + g;
            int n1 = n0 + 8;
            #pragma unroll
            for (int j = 0; j < 8; j++) {
                int col = nc8 + j * 8 + 2 * tig;
                float b0 = sb3[col], b1 = sb3[col + 1];
                if (n0 < NN) {
                    float2 v; v.x = c[j][0] + b0; v.y = c[j][1] + b1;
                    *(float2*)(out + (long)n0 * DD + col) = v;
                }
                if (n1 < NN) {
                    float2 v; v.x = c[j][2] + b0; v.y = c[j][3] + b1;
                    *(float2*)(out + (long)n1 * DD + col) = v;
                }
            }
        }
        pbar(p);    // protect sX before next iteration's gather
    }
}

extern "C" void kernel_launch(void* const* d_in, const int* in_sizes, int n_in,
                              void* d_out, int out_size) {
    const float* nf   = (const float*)d_in[0];
    const int*   esrc = (const int*)d_in[1];
    const int*   edst = (const int*)d_in[2];
    const int*   etyp = (const int*)d_in[3];
    const float* Wr1  = (const float*)d_in[4];
    const float* br1  = (const float*)d_in[5];
    const float* Wr2  = (const float*)d_in[6];
    const float* br2  = (const float*)d_in[7];
    const float* Wr3  = (const float*)d_in[8];
    const float* br3  = (const float*)d_in[9];
    const float* Wn1  = (const float*)d_in[10];
    const float* bn1  = (const float*)d_in[11];
    const float* Wn2  = (const float*)d_in[12];
    const float* bn2  = (const float*)d_in[13];
    const float* Wn3  = (const float*)d_in[14];
    const float* bn3  = (const float*)d_in[15];
    float* out = (float*)d_out;

    cudaFuncSetAttribute(edge_kernel, cudaFuncAttributeMaxDynamicSharedMemorySize, E_TOTAL);
    cudaFuncSetAttribute(node_kernel, cudaFuncAttributeMaxDynamicSharedMemorySize, N_TOTAL);

    void* accp = nullptr;  void* cntp = nullptr;
    cudaGetSymbolAddress(&accp, g_acc);
    cudaGetSymbolAddress(&cntp, g_cnt);
    cudaMemsetAsync(accp, 0, (size_t)NN * HH * sizeof(float));
    cudaMemsetAsync(cntp, 0, RR * sizeof(int));

    bin_kernel<<<(NE + NTHREADS - 1) / NTHREADS, NTHREADS>>>(etyp);
    edge_kernel<<<2 * NSM, NTHREADS, E_TOTAL>>>(nf, esrc, edst,
                                                Wr1, br1, Wr2, br2, Wr3, br3, Wn1);
    node_kernel<<<2 * NSM, NTHREADS, N_TOTAL>>>(nf, Wn1, bn1, Wn2, bn2, Wn3, bn3, out);
}